// round 2
// baseline (speedup 1.0000x reference)
#include <cuda_runtime.h>
#include <math.h>

// ---------------- problem constants ----------------
#define BATCH 8
#define DIMC 128
#define HGT 64
#define WID 64
#define HW 4096
#define M_TOT 32768       // BATCH*HGT*WID
#define K3 384

// ---------------- scratch (device globals; no allocation allowed) ----------------
__device__ float g_xcat[M_TOT * K3];   // [pix][384]  concat(lr, m, sr), K-contiguous
__device__ float g_x[M_TOT * DIMC];    // [pix][128]  post proj_in ReLU
__device__ float g_gxh[M_TOT * K3];    // [pix][384]  x @ wih_h^T + bih_h
__device__ float g_gxw[M_TOT * K3];    // [pix][384]  x @ wih_w^T + bih_w
__device__ float g_oh[M_TOT * DIMC];   // [pix][128]  vertical scan output
__device__ float g_ow[M_TOT * DIMC];   // [pix][128]  horizontal scan output

// ======================================================================
// Kernel 1: resize (antialias-down for l, bilinear-up for s) + concat
// Output layout: g_xcat[pix][c], c in [0,384): 0-127 lr, 128-255 m, 256-383 sr
// ======================================================================
__global__ void resize_concat_kernel(const float* __restrict__ l,
                                     const float* __restrict__ mid,
                                     const float* __restrict__ s,
                                     float* __restrict__ xcat)
{
    int idx = blockIdx.x * blockDim.x + threadIdx.x;
    if (idx >= M_TOT * K3) return;
    int c   = idx % K3;
    int pix = idx / K3;
    int w = pix & 63;
    int h = (pix >> 6) & 63;
    int b = pix >> 12;

    float v;
    if (c < 128) {
        // downsample 128->64 with antialias triangle: taps 2i-1..2i+2, raw {1,3,3,1}/8,
        // edge taps dropped and weights renormalized (matches jax.image.resize).
        int jh[4]; float wh[4];
        int jw[4]; float ww_[4];
        {
            float sum = 0.f;
            #pragma unroll
            for (int t = 0; t < 4; t++) {
                int jj = 2*h - 1 + t;
                float r = (t == 0 || t == 3) ? 0.25f : 0.75f;
                bool ok = (jj >= 0 && jj < 128);
                jh[t] = ok ? jj : 0;
                wh[t] = ok ? r : 0.f;
                sum += wh[t];
            }
            float inv = 1.f / sum;
            #pragma unroll
            for (int t = 0; t < 4; t++) wh[t] *= inv;
        }
        {
            float sum = 0.f;
            #pragma unroll
            for (int t = 0; t < 4; t++) {
                int jj = 2*w - 1 + t;
                float r = (t == 0 || t == 3) ? 0.25f : 0.75f;
                bool ok = (jj >= 0 && jj < 128);
                jw[t] = ok ? jj : 0;
                ww_[t] = ok ? r : 0.f;
                sum += ww_[t];
            }
            float inv = 1.f / sum;
            #pragma unroll
            for (int t = 0; t < 4; t++) ww_[t] *= inv;
        }
        const float* lp = l + ((size_t)(b*128 + c) << 14);   // 128*128 plane
        v = 0.f;
        #pragma unroll
        for (int a = 0; a < 4; a++) {
            float rowacc = 0.f;
            #pragma unroll
            for (int q = 0; q < 4; q++)
                rowacc += ww_[q] * lp[(jh[a] << 7) + jw[q]];
            v += wh[a] * rowacc;
        }
    } else if (c < 256) {
        v = mid[((size_t)(b*128 + (c-128)) << 12) + (h << 6) + w];
    } else {
        // upsample 32->64: pos = 0.5*i - 0.25, 2 taps, edge renormalized
        int jh[2]; float wh[2];
        int jw[2]; float ww_[2];
        {
            float p = 0.5f*h - 0.25f;
            int j0 = (int)floorf(p);
            float f = p - (float)j0;
            bool o0 = (j0 >= 0 && j0 < 32), o1 = (j0+1 >= 0 && j0+1 < 32);
            wh[0] = o0 ? (1.f - f) : 0.f; jh[0] = o0 ? j0 : 0;
            wh[1] = o1 ? f : 0.f;         jh[1] = o1 ? (j0+1) : 0;
            float inv = 1.f / (wh[0] + wh[1]);
            wh[0] *= inv; wh[1] *= inv;
        }
        {
            float p = 0.5f*w - 0.25f;
            int j0 = (int)floorf(p);
            float f = p - (float)j0;
            bool o0 = (j0 >= 0 && j0 < 32), o1 = (j0+1 >= 0 && j0+1 < 32);
            ww_[0] = o0 ? (1.f - f) : 0.f; jw[0] = o0 ? j0 : 0;
            ww_[1] = o1 ? f : 0.f;         jw[1] = o1 ? (j0+1) : 0;
            float inv = 1.f / (ww_[0] + ww_[1]);
            ww_[0] *= inv; ww_[1] *= inv;
        }
        const float* sp = s + ((size_t)(b*128 + (c-256)) << 10);  // 32*32 plane
        v = wh[0]*(ww_[0]*sp[(jh[0]<<5)+jw[0]] + ww_[1]*sp[(jh[0]<<5)+jw[1]])
          + wh[1]*(ww_[0]*sp[(jh[1]<<5)+jw[0]] + ww_[1]*sp[(jh[1]<<5)+jw[1]]);
    }
    xcat[idx] = v;
}

// ======================================================================
// NT GEMM: C[m][n] = sum_k A[m][k] * B[n][k], tile 64x128, 256 threads.
// EPI 0: relu(acc*p0[n] + p1[n])     (proj_in)
// EPI 1: acc + p0[n]                 (gx bias)
// ======================================================================
template<int K, int EPI>
__global__ void gemm_nt_kernel(const float* __restrict__ A,
                               const float* __restrict__ Bw,
                               const float* __restrict__ p0,
                               const float* __restrict__ p1,
                               float* __restrict__ C, int N)
{
    __shared__ float a_s[16*66];
    __shared__ float b_s[16*132];
    const int m0 = blockIdx.x * 64;
    const int n0 = blockIdx.y * 128;
    const int tid = threadIdx.x;
    const int tx = tid & 15, ty = tid >> 4;

    float acc[4][8];
    #pragma unroll
    for (int i = 0; i < 4; i++)
        #pragma unroll
        for (int j = 0; j < 8; j++) acc[i][j] = 0.f;

    for (int k0 = 0; k0 < K; k0 += 16) {
        {
            int mm = tid >> 2, kq = tid & 3;
            float4 v = *(const float4*)(A + (size_t)(m0+mm)*K + k0 + kq*4);
            a_s[(kq*4+0)*66+mm] = v.x;
            a_s[(kq*4+1)*66+mm] = v.y;
            a_s[(kq*4+2)*66+mm] = v.z;
            a_s[(kq*4+3)*66+mm] = v.w;
        }
        #pragma unroll
        for (int r = 0; r < 2; r++) {
            int id2 = tid + r*256;
            int nn = id2 >> 2, kq = id2 & 3;
            float4 v = *(const float4*)(Bw + (size_t)(n0+nn)*K + k0 + kq*4);
            b_s[(kq*4+0)*132+nn] = v.x;
            b_s[(kq*4+1)*132+nn] = v.y;
            b_s[(kq*4+2)*132+nn] = v.z;
            b_s[(kq*4+3)*132+nn] = v.w;
        }
        __syncthreads();
        #pragma unroll
        for (int kk = 0; kk < 16; kk++) {
            float av[4], bv[8];
            #pragma unroll
            for (int i = 0; i < 4; i++) av[i] = a_s[kk*66 + ty + 16*i];
            #pragma unroll
            for (int j = 0; j < 8; j++) bv[j] = b_s[kk*132 + tx + 16*j];
            #pragma unroll
            for (int i = 0; i < 4; i++)
                #pragma unroll
                for (int j = 0; j < 8; j++)
                    acc[i][j] = fmaf(av[i], bv[j], acc[i][j]);
        }
        __syncthreads();
    }

    #pragma unroll
    for (int i = 0; i < 4; i++) {
        int mm = m0 + ty + 16*i;
        #pragma unroll
        for (int j = 0; j < 8; j++) {
            int nn = n0 + tx + 16*j;
            float v = acc[i][j];
            if (EPI == 0) v = fmaxf(fmaf(v, p0[nn], p1[nn]), 0.f);
            else          v = v + p0[nn];
            C[(size_t)mm*N + nn] = v;
        }
    }
}

// ======================================================================
// Scan kernel: 128 blocks (64 vertical + 64 horizontal), 128 threads.
// Each block: 8 independent sequences, whh staged in smem (row pad 129),
// hidden state transposed h_t[k][8]. Thread c owns channel c (gates c, c+128, c+256).
// ======================================================================
#define SCAN_SMEM ((384*129 + 128*8) * 4)

__global__ void scan_kernel(const float* __restrict__ whh_h,
                            const float* __restrict__ bhh_h,
                            const float* __restrict__ whh_w,
                            const float* __restrict__ bhh_w,
                            const float* __restrict__ gxh,
                            const float* __restrict__ gxw,
                            float* __restrict__ ohp,
                            float* __restrict__ owp)
{
    extern __shared__ float sm[];
    float* whh_s = sm;                 // [384][129]
    float* h_t   = sm + 384*129;       // [128][8], k-major

    const int dir = blockIdx.x >> 6;
    const int sub = blockIdx.x & 63;
    const int b   = sub >> 3;
    const int q0  = (sub & 7) << 3;    // 8 sequences q0..q0+7

    const float* whh = dir ? whh_w : whh_h;
    const float* bhh = dir ? bhh_w : bhh_h;
    const float* gx  = dir ? gxw : gxh;
    float* outp      = dir ? owp : ohp;

    const int c = threadIdx.x;

    // stage whh -> smem, padded rows of 129 (conflict-free column reads)
    for (int i = c; i < 384*32; i += 128) {
        int g = i >> 5, kq = i & 31;
        float4 v = *(const float4*)(whh + g*128 + kq*4);
        whh_s[g*129 + kq*4 + 0] = v.x;
        whh_s[g*129 + kq*4 + 1] = v.y;
        whh_s[g*129 + kq*4 + 2] = v.z;
        whh_s[g*129 + kq*4 + 3] = v.w;
    }
    #pragma unroll
    for (int s2 = 0; s2 < 8; s2++) h_t[c*8 + s2] = 0.f;

    const float bh_r = bhh[c];
    const float bh_z = bhh[c + 128];
    const float bh_n = bhh[c + 256];
    __syncthreads();

    const float* wr = whh_s + (size_t)c*129;
    const float* wz = whh_s + (size_t)(c+128)*129;
    const float* wn = whh_s + (size_t)(c+256)*129;

    // prefetch gx for step 0
    float nr[8], nz[8], nn_[8];
    #pragma unroll
    for (int s2 = 0; s2 < 8; s2++) {
        int pix = dir ? ((b*64 + q0+s2)*64 + 0) : ((b*64 + 0)*64 + q0+s2);
        const float* gp = gx + (size_t)pix * K3;
        nr[s2] = gp[c]; nz[s2] = gp[128+c]; nn_[s2] = gp[256+c];
    }

    for (int t = 0; t < 64; t++) {
        float cr[8], cz[8], cn[8];
        #pragma unroll
        for (int s2 = 0; s2 < 8; s2++) { cr[s2]=nr[s2]; cz[s2]=nz[s2]; cn[s2]=nn_[s2]; }
        if (t < 63) {
            #pragma unroll
            for (int s2 = 0; s2 < 8; s2++) {
                int pix = dir ? ((b*64 + q0+s2)*64 + (t+1)) : ((b*64 + (t+1))*64 + q0+s2);
                const float* gp = gx + (size_t)pix * K3;
                nr[s2] = gp[c]; nz[s2] = gp[128+c]; nn_[s2] = gp[256+c];
            }
        }

        float sr[8], sz[8], sn[8];
        #pragma unroll
        for (int s2 = 0; s2 < 8; s2++) { sr[s2]=0.f; sz[s2]=0.f; sn[s2]=0.f; }

        #pragma unroll 4
        for (int k = 0; k < 128; k++) {
            float4 ha = *(const float4*)(h_t + k*8);
            float4 hb = *(const float4*)(h_t + k*8 + 4);
            float a = wr[k], bz = wz[k], cn_w = wn[k];
            sr[0] = fmaf(ha.x, a, sr[0]); sr[1] = fmaf(ha.y, a, sr[1]);
            sr[2] = fmaf(ha.z, a, sr[2]); sr[3] = fmaf(ha.w, a, sr[3]);
            sr[4] = fmaf(hb.x, a, sr[4]); sr[5] = fmaf(hb.y, a, sr[5]);
            sr[6] = fmaf(hb.z, a, sr[6]); sr[7] = fmaf(hb.w, a, sr[7]);
            sz[0] = fmaf(ha.x, bz, sz[0]); sz[1] = fmaf(ha.y, bz, sz[1]);
            sz[2] = fmaf(ha.z, bz, sz[2]); sz[3] = fmaf(ha.w, bz, sz[3]);
            sz[4] = fmaf(hb.x, bz, sz[4]); sz[5] = fmaf(hb.y, bz, sz[5]);
            sz[6] = fmaf(hb.z, bz, sz[6]); sz[7] = fmaf(hb.w, bz, sz[7]);
            sn[0] = fmaf(ha.x, cn_w, sn[0]); sn[1] = fmaf(ha.y, cn_w, sn[1]);
            sn[2] = fmaf(ha.z, cn_w, sn[2]); sn[3] = fmaf(ha.w, cn_w, sn[3]);
            sn[4] = fmaf(hb.x, cn_w, sn[4]); sn[5] = fmaf(hb.y, cn_w, sn[5]);
            sn[6] = fmaf(hb.z, cn_w, sn[6]); sn[7] = fmaf(hb.w, cn_w, sn[7]);
        }

        float hnew[8];
        #pragma unroll
        for (int s2 = 0; s2 < 8; s2++) {
            float hold = h_t[c*8 + s2];
            float rpre = cr[s2] + sr[s2] + bh_r;
            float zpre = cz[s2] + sz[s2] + bh_z;
            float r = 1.f / (1.f + __expf(-rpre));
            float z = 1.f / (1.f + __expf(-zpre));
            float n = tanhf(cn[s2] + r * (sn[s2] + bh_n));
            hnew[s2] = (1.f - z) * n + z * hold;
        }
        __syncthreads();   // all reads of h_t done
        #pragma unroll
        for (int s2 = 0; s2 < 8; s2++) h_t[c*8 + s2] = hnew[s2];
        #pragma unroll
        for (int s2 = 0; s2 < 8; s2++) {
            int pix = dir ? ((b*64 + q0+s2)*64 + t) : ((b*64 + t)*64 + q0+s2);
            outp[(size_t)pix*DIMC + c] = hnew[s2];
        }
        __syncthreads();   // h_t writes visible before next step
    }
}

// ======================================================================
// Tail: scanned = oh+ow; gate = sigmoid(scanned@gate_w^T + gb);
// gated = scanned*gate; y = relu(gated@pw^T * pscale + pshift) + x;
// transposed (channel-major) write to out[b][c][h][w].
// ======================================================================
#define TAIL_SMEM ((2*64*130 + 16*132 + 128*66) * 4)

__global__ void tail_kernel(const float* __restrict__ ohp,
                            const float* __restrict__ owp,
                            const float* __restrict__ xres,
                            const float* __restrict__ gate_w,
                            const float* __restrict__ gate_b,
                            const float* __restrict__ pw,
                            const float* __restrict__ pscale,
                            const float* __restrict__ pshift,
                            float* __restrict__ out)
{
    extern __shared__ float sm[];
    float* s_full = sm;                 // [64][130] scanned
    float* g_full = sm + 64*130;        // [64][130] gated
    float* w_s    = sm + 2*64*130;      // [16][132]
    float* st     = w_s + 16*132;       // [128][66] transposed stage

    const int m0  = blockIdx.x * 64;
    const int b   = m0 >> 12;
    const int hw0 = m0 & 4095;
    const int tid = threadIdx.x;
    const int tx = tid & 15, ty = tid >> 4;

    for (int i = tid; i < 64*32; i += 256) {
        int mm = i >> 5, kq = i & 31;
        float4 a = *(const float4*)(ohp + (size_t)(m0+mm)*DIMC + kq*4);
        float4 c = *(const float4*)(owp + (size_t)(m0+mm)*DIMC + kq*4);
        s_full[mm*130 + kq*4 + 0] = a.x + c.x;
        s_full[mm*130 + kq*4 + 1] = a.y + c.y;
        s_full[mm*130 + kq*4 + 2] = a.z + c.z;
        s_full[mm*130 + kq*4 + 3] = a.w + c.w;
    }
    __syncthreads();

    // GEMM1: scanned @ gate_w^T
    float acc[4][8];
    #pragma unroll
    for (int i = 0; i < 4; i++)
        #pragma unroll
        for (int j = 0; j < 8; j++) acc[i][j] = 0.f;

    for (int k0 = 0; k0 < 128; k0 += 16) {
        #pragma unroll
        for (int r = 0; r < 2; r++) {
            int id2 = tid + r*256;
            int nn = id2 >> 2, kq = id2 & 3;
            float4 v = *(const float4*)(gate_w + (size_t)nn*128 + k0 + kq*4);
            w_s[(kq*4+0)*132+nn] = v.x;
            w_s[(kq*4+1)*132+nn] = v.y;
            w_s[(kq*4+2)*132+nn] = v.z;
            w_s[(kq*4+3)*132+nn] = v.w;
        }
        __syncthreads();
        #pragma unroll
        for (int kk = 0; kk < 16; kk++) {
            float av[4], bv[8];
            #pragma unroll
            for (int i = 0; i < 4; i++) av[i] = s_full[(ty+16*i)*130 + k0 + kk];
            #pragma unroll
            for (int j = 0; j < 8; j++) bv[j] = w_s[kk*132 + tx + 16*j];
            #pragma unroll
            for (int i = 0; i < 4; i++)
                #pragma unroll
                for (int j = 0; j < 8; j++)
                    acc[i][j] = fmaf(av[i], bv[j], acc[i][j]);
        }
        __syncthreads();
    }

    #pragma unroll
    for (int i = 0; i < 4; i++) {
        int mm = ty + 16*i;
        #pragma unroll
        for (int j = 0; j < 8; j++) {
            int nn = tx + 16*j;
            float g = 1.f / (1.f + __expf(-(acc[i][j] + gate_b[nn])));
            g_full[mm*130 + nn] = s_full[mm*130 + nn] * g;
        }
    }
    __syncthreads();

    // GEMM2: gated @ pw^T
    float acc2[4][8];
    #pragma unroll
    for (int i = 0; i < 4; i++)
        #pragma unroll
        for (int j = 0; j < 8; j++) acc2[i][j] = 0.f;

    for (int k0 = 0; k0 < 128; k0 += 16) {
        #pragma unroll
        for (int r = 0; r < 2; r++) {
            int id2 = tid + r*256;
            int nn = id2 >> 2, kq = id2 & 3;
            float4 v = *(const float4*)(pw + (size_t)nn*128 + k0 + kq*4);
            w_s[(kq*4+0)*132+nn] = v.x;
            w_s[(kq*4+1)*132+nn] = v.y;
            w_s[(kq*4+2)*132+nn] = v.z;
            w_s[(kq*4+3)*132+nn] = v.w;
        }
        __syncthreads();
        #pragma unroll
        for (int kk = 0; kk < 16; kk++) {
            float av[4], bv[8];
            #pragma unroll
            for (int i = 0; i < 4; i++) av[i] = g_full[(ty+16*i)*130 + k0 + kk];
            #pragma unroll
            for (int j = 0; j < 8; j++) bv[j] = w_s[kk*132 + tx + 16*j];
            #pragma unroll
            for (int i = 0; i < 4; i++)
                #pragma unroll
                for (int j = 0; j < 8; j++)
                    acc2[i][j] = fmaf(av[i], bv[j], acc2[i][j]);
        }
        __syncthreads();
    }

    #pragma unroll
    for (int i = 0; i < 4; i++) {
        int mm = ty + 16*i;
        #pragma unroll
        for (int j = 0; j < 8; j++) {
            int nn = tx + 16*j;
            float v = fmaxf(fmaf(acc2[i][j], pscale[nn], pshift[nn]), 0.f)
                    + xres[(size_t)(m0+mm)*DIMC + nn];
            st[nn*66 + mm] = v;
        }
    }
    __syncthreads();

    for (int i = tid; i < 128*64; i += 256) {
        int nn = i >> 6, mm = i & 63;
        out[(size_t)(b*128 + nn)*HW + hw0 + mm] = st[nn*66 + mm];
    }
}

// ======================================================================
// Launch
// ======================================================================
extern "C" void kernel_launch(void* const* d_in, const int* in_sizes, int n_in,
                              void* d_out, int out_size)
{
    const float* l     = (const float*)d_in[0];
    const float* m_    = (const float*)d_in[1];
    const float* s_    = (const float*)d_in[2];
    const float* piw   = (const float*)d_in[3];
    const float* pisc  = (const float*)d_in[4];
    const float* pish  = (const float*)d_in[5];
    const float* wih_h = (const float*)d_in[6];
    const float* whh_h = (const float*)d_in[7];
    const float* bih_h = (const float*)d_in[8];
    const float* bhh_h = (const float*)d_in[9];
    const float* wih_w = (const float*)d_in[10];
    const float* whh_w = (const float*)d_in[11];
    const float* bih_w = (const float*)d_in[12];
    const float* bhh_w = (const float*)d_in[13];
    const float* gw    = (const float*)d_in[14];
    const float* gb    = (const float*)d_in[15];
    const float* pow_  = (const float*)d_in[16];
    const float* posc  = (const float*)d_in[17];
    const float* posh  = (const float*)d_in[18];
    float* out = (float*)d_out;

    void *p_xcat, *p_x, *p_gxh, *p_gxw, *p_oh, *p_ow;
    cudaGetSymbolAddress(&p_xcat, g_xcat);
    cudaGetSymbolAddress(&p_x,    g_x);
    cudaGetSymbolAddress(&p_gxh,  g_gxh);
    cudaGetSymbolAddress(&p_gxw,  g_gxw);
    cudaGetSymbolAddress(&p_oh,   g_oh);
    cudaGetSymbolAddress(&p_ow,   g_ow);
    float* xcat = (float*)p_xcat;
    float* x    = (float*)p_x;
    float* gxh  = (float*)p_gxh;
    float* gxw  = (float*)p_gxw;
    float* oh   = (float*)p_oh;
    float* ow   = (float*)p_ow;

    cudaFuncSetAttribute(scan_kernel, cudaFuncAttributeMaxDynamicSharedMemorySize, SCAN_SMEM);
    cudaFuncSetAttribute(tail_kernel, cudaFuncAttributeMaxDynamicSharedMemorySize, TAIL_SMEM);

    // 1. resize + concat
    resize_concat_kernel<<<(M_TOT*K3)/256, 256>>>(l, m_, s_, xcat);

    // 2. proj_in: x = relu((xcat @ piw^T) * scale + shift)
    gemm_nt_kernel<K3, 0><<<dim3(M_TOT/64, 1), 256>>>(xcat, piw, pisc, pish, x, DIMC);

    // 3. gx precompute for both scan directions
    gemm_nt_kernel<DIMC, 1><<<dim3(M_TOT/64, 3), 256>>>(x, wih_h, bih_h, nullptr, gxh, K3);
    gemm_nt_kernel<DIMC, 1><<<dim3(M_TOT/64, 3), 256>>>(x, wih_w, bih_w, nullptr, gxw, K3);

    // 4. both GRU scans concurrently (blocks 0-63 vertical, 64-127 horizontal)
    scan_kernel<<<128, 128, SCAN_SMEM>>>(whh_h, bhh_h, whh_w, bhh_w, gxh, gxw, oh, ow);

    // 5. gate + proj_out + residual + transposed store
    tail_kernel<<<M_TOT/64, 256, TAIL_SMEM>>>(oh, ow, x, gw, gb, pow_, posc, posh, out);
}

// round 4
// speedup vs baseline: 1.1666x; 1.1666x over previous
#include <cuda_runtime.h>
#include <cuda_bf16.h>
#include <math.h>
#include <stdint.h>

// ---------------- problem constants ----------------
#define BATCH 8
#define DIMC 128
#define HGT 64
#define WID 64
#define HW 4096
#define M_TOT 32768       // BATCH*HGT*WID
#define K3 384

// ---------------- scratch (device globals; no allocation allowed) ----------------
__device__ float g_xcat[M_TOT * K3];   // [pix][384]
__device__ float g_x[M_TOT * DIMC];    // [pix][128]
__device__ float g_gxh[M_TOT * K3];
__device__ float g_gxw[M_TOT * K3];
__device__ float g_oh[M_TOT * DIMC];
__device__ float g_ow[M_TOT * DIMC];

// ======================================================================
// helpers
// ======================================================================
__device__ __forceinline__ uint32_t smem_u32(const void* p) {
    uint32_t a;
    asm("{ .reg .u64 t; cvta.to.shared.u64 t, %1; cvt.u32.u64 %0, t; }"
        : "=r"(a) : "l"(p));
    return a;
}

__device__ __forceinline__ void ldsm4(uint32_t* r, uint32_t addr) {
    asm volatile("ldmatrix.sync.aligned.m8n8.x4.shared.b16 {%0,%1,%2,%3}, [%4];"
                 : "=r"(r[0]), "=r"(r[1]), "=r"(r[2]), "=r"(r[3]) : "r"(addr));
}

__device__ __forceinline__ void mma16816(float* c, const uint32_t* a, const uint32_t* b) {
    asm volatile(
        "mma.sync.aligned.m16n8k16.row.col.f32.bf16.bf16.f32 "
        "{%0,%1,%2,%3}, {%4,%5,%6,%7}, {%8,%9}, {%0,%1,%2,%3};"
        : "+f"(c[0]), "+f"(c[1]), "+f"(c[2]), "+f"(c[3])
        : "r"(a[0]), "r"(a[1]), "r"(a[2]), "r"(a[3]), "r"(b[0]), "r"(b[1]));
}

// convert 8 consecutive fp32 -> bf16 hi + bf16 lo residual (16B each)
__device__ __forceinline__ void cvt8(__nv_bfloat16* hi, __nv_bfloat16* lo,
                                     const float* __restrict__ src) {
    float4 va = *(const float4*)(src);
    float4 vb = *(const float4*)(src + 4);
    float f[8] = {va.x, va.y, va.z, va.w, vb.x, vb.y, vb.z, vb.w};
    uint32_t h[4], l[4];
#pragma unroll
    for (int i = 0; i < 4; i++) {
        unsigned short b0 = __bfloat16_as_ushort(__float2bfloat16(f[2*i]));
        unsigned short b1 = __bfloat16_as_ushort(__float2bfloat16(f[2*i+1]));
        h[i] = ((uint32_t)b1 << 16) | (uint32_t)b0;
        float la = f[2*i]   - __uint_as_float((uint32_t)b0 << 16);
        float lb = f[2*i+1] - __uint_as_float((uint32_t)b1 << 16);
        unsigned short c0 = __bfloat16_as_ushort(__float2bfloat16(la));
        unsigned short c1 = __bfloat16_as_ushort(__float2bfloat16(lb));
        l[i] = ((uint32_t)c1 << 16) | (uint32_t)c0;
    }
    *(uint4*)hi = make_uint4(h[0], h[1], h[2], h[3]);
    *(uint4*)lo = make_uint4(l[0], l[1], l[2], l[3]);
}

// ======================================================================
// bf16x3 warp-MMA NT GEMM: C[128, NTILES*64] per block, K = KSLABS*128.
// A fp32 [., lda] K-contiguous; B fp32 [n][ldb] (weights, NT).
// EPI 0: relu(acc*p0[n]+p1[n]); EPI 1: acc + p0[n].
// smem rows padded to 136 bf16 (272B) -> conflict-free ldmatrix.
// ======================================================================
#define SA_STRIDE 136
#define MMA_SMEM (104448)   // 2*(128*136*2) + 2*(64*136*2)

template<int KSLABS, int NTILES, int EPI>
__device__ void mma_core(const float* __restrict__ A0, int lda,
                         const float* __restrict__ B0, int ldb,
                         const float* __restrict__ p0, const float* __restrict__ p1,
                         float* __restrict__ C0, int ldc)
{
    extern __shared__ char smraw[];
    __nv_bfloat16* sa_hi = (__nv_bfloat16*)(smraw);
    __nv_bfloat16* sa_lo = (__nv_bfloat16*)(smraw + 34816);
    __nv_bfloat16* sb_hi = (__nv_bfloat16*)(smraw + 69632);
    __nv_bfloat16* sb_lo = (__nv_bfloat16*)(smraw + 87040);
    const uint32_t sbase = smem_u32(smraw);
    const uint32_t u_sa_hi = sbase;
    const uint32_t u_sa_lo = sbase + 34816;
    const uint32_t u_sb_hi = sbase + 69632;
    const uint32_t u_sb_lo = sbase + 87040;

    const int tid  = threadIdx.x;
    const int wid  = tid >> 5;
    const int lane = tid & 31;
    const int wm = wid >> 1;       // 0..3  (M group of 32)
    const int wn = wid & 1;        // 0..1  (N group of 32)
    const int gid = lane >> 2, tig = lane & 3;

#pragma unroll 1
    for (int nt = 0; nt < NTILES; nt++) {
        float acc[2][4][4];
#pragma unroll
        for (int i = 0; i < 2; i++)
#pragma unroll
            for (int j = 0; j < 4; j++)
#pragma unroll
                for (int e = 0; e < 4; e++) acc[i][j][e] = 0.f;

#pragma unroll 1
        for (int s = 0; s < KSLABS; s++) {
            __syncthreads();
            if (nt == 0 || KSLABS > 1) {
                // A slab: 128 rows x 128 cols; thread t: row t>>1, 64 cols
                int row = tid >> 1, cb = (tid & 1) * 64;
                const float* src = A0 + (size_t)row * lda + s * 128 + cb;
                __nv_bfloat16* dh = sa_hi + row * SA_STRIDE + cb;
                __nv_bfloat16* dl = sa_lo + row * SA_STRIDE + cb;
#pragma unroll
                for (int j = 0; j < 8; j++) cvt8(dh + j*8, dl + j*8, src + j*8);
            }
            {
                // B tile: 64 rows x 128 cols; thread t: row t>>2, 32 cols
                int row = tid >> 2, cb = (tid & 3) * 32;
                const float* src = B0 + (size_t)(nt * 64 + row) * ldb + s * 128 + cb;
                __nv_bfloat16* dh = sb_hi + row * SA_STRIDE + cb;
                __nv_bfloat16* dl = sb_lo + row * SA_STRIDE + cb;
#pragma unroll
                for (int j = 0; j < 4; j++) cvt8(dh + j*8, dl + j*8, src + j*8);
            }
            __syncthreads();

#pragma unroll
            for (int ch = 0; ch < 8; ch++) {
                const int k = ch * 16;
                uint32_t ah[2][4], al[2][4];
#pragma unroll
                for (int i = 0; i < 2; i++) {
                    uint32_t off = (uint32_t)(((wm*32 + i*16 + (lane & 15)) * SA_STRIDE
                                               + k + ((lane >> 4) << 3)) * 2);
                    ldsm4(ah[i], u_sa_hi + off);
                    ldsm4(al[i], u_sa_lo + off);
                }
                uint32_t bh[4][2], bl[4][2];
#pragma unroll
                for (int nb = 0; nb < 2; nb++) {
                    int row = wn*32 + nb*16 + (lane & 7) + ((lane >> 4) << 3);
                    int col = k + ((lane >> 3) & 1) * 8;
                    uint32_t off = (uint32_t)((row * SA_STRIDE + col) * 2);
                    uint32_t r[4];
                    ldsm4(r, u_sb_hi + off);
                    bh[2*nb][0] = r[0]; bh[2*nb][1] = r[1];
                    bh[2*nb+1][0] = r[2]; bh[2*nb+1][1] = r[3];
                    ldsm4(r, u_sb_lo + off);
                    bl[2*nb][0] = r[0]; bl[2*nb][1] = r[1];
                    bl[2*nb+1][0] = r[2]; bl[2*nb+1][1] = r[3];
                }
#pragma unroll
                for (int i = 0; i < 2; i++)
#pragma unroll
                    for (int j = 0; j < 4; j++) {
                        mma16816(acc[i][j], ah[i], bh[j]);
                        mma16816(acc[i][j], ah[i], bl[j]);
                        mma16816(acc[i][j], al[i], bh[j]);
                    }
            }
        }

        // epilogue
#pragma unroll
        for (int i = 0; i < 2; i++) {
            int mrow = wm*32 + i*16 + gid;
#pragma unroll
            for (int j = 0; j < 4; j++) {
                int ncol = nt*64 + wn*32 + j*8 + tig*2;
                float2 q0 = *(const float2*)(p0 + ncol);
                float2 q1 = (EPI == 0) ? *(const float2*)(p1 + ncol)
                                       : make_float2(0.f, 0.f);
                float v0, v1, v2, v3;
                if (EPI == 0) {
                    v0 = fmaxf(fmaf(acc[i][j][0], q0.x, q1.x), 0.f);
                    v1 = fmaxf(fmaf(acc[i][j][1], q0.y, q1.y), 0.f);
                    v2 = fmaxf(fmaf(acc[i][j][2], q0.x, q1.x), 0.f);
                    v3 = fmaxf(fmaf(acc[i][j][3], q0.y, q1.y), 0.f);
                } else {
                    v0 = acc[i][j][0] + q0.x;
                    v1 = acc[i][j][1] + q0.y;
                    v2 = acc[i][j][2] + q0.x;
                    v3 = acc[i][j][3] + q0.y;
                }
                *(float2*)(C0 + (size_t)mrow * ldc + ncol) = make_float2(v0, v1);
                *(float2*)(C0 + (size_t)(mrow + 8) * ldc + ncol) = make_float2(v2, v3);
            }
        }
    }
}

__global__ void __launch_bounds__(256)
mma_proj_kernel(const float* __restrict__ xcat, const float* __restrict__ piw,
                const float* __restrict__ pisc, const float* __restrict__ pish,
                float* __restrict__ x)
{
    mma_core<3, 2, 0>(xcat + (size_t)blockIdx.x * 128 * K3, K3,
                      piw, K3, pisc, pish,
                      x + (size_t)blockIdx.x * 128 * DIMC, DIMC);
}

__global__ void __launch_bounds__(256)
mma_gx_kernel(const float* __restrict__ x,
              const float* __restrict__ wih_h, const float* __restrict__ bih_h,
              const float* __restrict__ wih_w, const float* __restrict__ bih_w,
              float* __restrict__ gxh, float* __restrict__ gxw)
{
    const float* B    = blockIdx.y ? wih_w : wih_h;
    const float* bias = blockIdx.y ? bih_w : bih_h;
    float* out        = blockIdx.y ? gxw : gxh;
    mma_core<1, 6, 1>(x + (size_t)blockIdx.x * 128 * DIMC, DIMC,
                      B, DIMC, bias, nullptr,
                      out + (size_t)blockIdx.x * 128 * K3, K3);
}

// ======================================================================
// resize (antialias-down for l, bilinear-up for s) + concat
// ======================================================================
__global__ void resize_concat_kernel(const float* __restrict__ l,
                                     const float* __restrict__ mid,
                                     const float* __restrict__ s,
                                     float* __restrict__ xcat)
{
    int idx = blockIdx.x * blockDim.x + threadIdx.x;
    if (idx >= M_TOT * K3) return;
    int c   = idx % K3;
    int pix = idx / K3;
    int w = pix & 63;
    int h = (pix >> 6) & 63;
    int b = pix >> 12;

    float v;
    if (c < 128) {
        int jh[4]; float wh[4];
        int jw[4]; float ww_[4];
        {
            float sum = 0.f;
            #pragma unroll
            for (int t = 0; t < 4; t++) {
                int jj = 2*h - 1 + t;
                float r = (t == 0 || t == 3) ? 0.25f : 0.75f;
                bool ok = (jj >= 0 && jj < 128);
                jh[t] = ok ? jj : 0;
                wh[t] = ok ? r : 0.f;
                sum += wh[t];
            }
            float inv = 1.f / sum;
            #pragma unroll
            for (int t = 0; t < 4; t++) wh[t] *= inv;
        }
        {
            float sum = 0.f;
            #pragma unroll
            for (int t = 0; t < 4; t++) {
                int jj = 2*w - 1 + t;
                float r = (t == 0 || t == 3) ? 0.25f : 0.75f;
                bool ok = (jj >= 0 && jj < 128);
                jw[t] = ok ? jj : 0;
                ww_[t] = ok ? r : 0.f;
                sum += ww_[t];
            }
            float inv = 1.f / sum;
            #pragma unroll
            for (int t = 0; t < 4; t++) ww_[t] *= inv;
        }
        const float* lp = l + ((size_t)(b*128 + c) << 14);
        v = 0.f;
        #pragma unroll
        for (int a = 0; a < 4; a++) {
            float rowacc = 0.f;
            #pragma unroll
            for (int q = 0; q < 4; q++)
                rowacc += ww_[q] * lp[(jh[a] << 7) + jw[q]];
            v += wh[a] * rowacc;
        }
    } else if (c < 256) {
        v = mid[((size_t)(b*128 + (c-128)) << 12) + (h << 6) + w];
    } else {
        int jh[2]; float wh[2];
        int jw[2]; float ww_[2];
        {
            float p = 0.5f*h - 0.25f;
            int j0 = (int)floorf(p);
            float f = p - (float)j0;
            bool o0 = (j0 >= 0 && j0 < 32), o1 = (j0+1 >= 0 && j0+1 < 32);
            wh[0] = o0 ? (1.f - f) : 0.f; jh[0] = o0 ? j0 : 0;
            wh[1] = o1 ? f : 0.f;         jh[1] = o1 ? (j0+1) : 0;
            float inv = 1.f / (wh[0] + wh[1]);
            wh[0] *= inv; wh[1] *= inv;
        }
        {
            float p = 0.5f*w - 0.25f;
            int j0 = (int)floorf(p);
            float f = p - (float)j0;
            bool o0 = (j0 >= 0 && j0 < 32), o1 = (j0+1 >= 0 && j0+1 < 32);
            ww_[0] = o0 ? (1.f - f) : 0.f; jw[0] = o0 ? j0 : 0;
            ww_[1] = o1 ? f : 0.f;         jw[1] = o1 ? (j0+1) : 0;
            float inv = 1.f / (ww_[0] + ww_[1]);
            ww_[0] *= inv; ww_[1] *= inv;
        }
        const float* sp = s + ((size_t)(b*128 + (c-256)) << 10);
        v = wh[0]*(ww_[0]*sp[(jh[0]<<5)+jw[0]] + ww_[1]*sp[(jh[0]<<5)+jw[1]])
          + wh[1]*(ww_[0]*sp[(jh[1]<<5)+jw[0]] + ww_[1]*sp[(jh[1]<<5)+jw[1]]);
    }
    xcat[idx] = v;
}

// ======================================================================
// Scan kernel with packed f32x2 FMA: 128 blocks, 128 threads
// ======================================================================
#define SCAN_SMEM ((384*129 + 128*8) * 4)

#define FMA2(acc, a, b) \
    asm volatile("fma.rn.f32x2 %0, %1, %2, %0;" : "+l"(acc) : "l"(a), "l"(b))
#define PACK2(d, f) \
    asm volatile("mov.b64 %0, {%1, %1};" : "=l"(d) : "r"(__float_as_uint(f)))

__global__ void scan_kernel(const float* __restrict__ whh_h,
                            const float* __restrict__ bhh_h,
                            const float* __restrict__ whh_w,
                            const float* __restrict__ bhh_w,
                            const float* __restrict__ gxh,
                            const float* __restrict__ gxw,
                            float* __restrict__ ohp,
                            float* __restrict__ owp)
{
    extern __shared__ float sm[];
    float* whh_s = sm;                 // [384][129]
    float* h_t   = sm + 384*129;       // [128][8]

    const int dir = blockIdx.x >> 6;
    const int sub = blockIdx.x & 63;
    const int b   = sub >> 3;
    const int q0  = (sub & 7) << 3;

    const float* whh = dir ? whh_w : whh_h;
    const float* bhh = dir ? bhh_w : bhh_h;
    const float* gx  = dir ? gxw : gxh;
    float* outp      = dir ? owp : ohp;

    const int c = threadIdx.x;

    for (int i = c; i < 384*32; i += 128) {
        int g = i >> 5, kq = i & 31;
        float4 v = *(const float4*)(whh + g*128 + kq*4);
        whh_s[g*129 + kq*4 + 0] = v.x;
        whh_s[g*129 + kq*4 + 1] = v.y;
        whh_s[g*129 + kq*4 + 2] = v.z;
        whh_s[g*129 + kq*4 + 3] = v.w;
    }
    #pragma unroll
    for (int s2 = 0; s2 < 8; s2++) h_t[c*8 + s2] = 0.f;

    const float bh_r = bhh[c];
    const float bh_z = bhh[c + 128];
    const float bh_n = bhh[c + 256];
    __syncthreads();

    const float* wr = whh_s + (size_t)c*129;
    const float* wz = whh_s + (size_t)(c+128)*129;
    const float* wn = whh_s + (size_t)(c+256)*129;

    float nr[8], nz[8], nn_[8];
    #pragma unroll
    for (int s2 = 0; s2 < 8; s2++) {
        int pix = dir ? ((b*64 + q0+s2)*64 + 0) : ((b*64 + 0)*64 + q0+s2);
        const float* gp = gx + (size_t)pix * K3;
        nr[s2] = gp[c]; nz[s2] = gp[128+c]; nn_[s2] = gp[256+c];
    }

    for (int t = 0; t < 64; t++) {
        float cr[8], cz[8], cn[8];
        #pragma unroll
        for (int s2 = 0; s2 < 8; s2++) { cr[s2]=nr[s2]; cz[s2]=nz[s2]; cn[s2]=nn_[s2]; }
        if (t < 63) {
            #pragma unroll
            for (int s2 = 0; s2 < 8; s2++) {
                int pix = dir ? ((b*64 + q0+s2)*64 + (t+1)) : ((b*64 + (t+1))*64 + q0+s2);
                const float* gp = gx + (size_t)pix * K3;
                nr[s2] = gp[c]; nz[s2] = gp[128+c]; nn_[s2] = gp[256+c];
            }
        }

        unsigned long long ar0=0,ar1=0,ar2=0,ar3=0;
        unsigned long long az0=0,az1=0,az2=0,az3=0;
        unsigned long long an0=0,an1=0,an2=0,an3=0;

        #pragma unroll 4
        for (int k = 0; k < 128; k++) {
            const ulonglong2* hp = reinterpret_cast<const ulonglong2*>(h_t + k*8);
            ulonglong2 hA = hp[0];
            ulonglong2 hB = hp[1];
            unsigned long long wr2, wz2, wn2;
            PACK2(wr2, wr[k]);
            PACK2(wz2, wz[k]);
            PACK2(wn2, wn[k]);
            FMA2(ar0, hA.x, wr2); FMA2(ar1, hA.y, wr2);
            FMA2(ar2, hB.x, wr2); FMA2(ar3, hB.y, wr2);
            FMA2(az0, hA.x, wz2); FMA2(az1, hA.y, wz2);
            FMA2(az2, hB.x, wz2); FMA2(az3, hB.y, wz2);
            FMA2(an0, hA.x, wn2); FMA2(an1, hA.y, wn2);
            FMA2(an2, hB.x, wn2); FMA2(an3, hB.y, wn2);
        }

        float sr[8], sz[8], sn[8];
        {
            float2 f;
            f = *reinterpret_cast<float2*>(&ar0); sr[0]=f.x; sr[1]=f.y;
            f = *reinterpret_cast<float2*>(&ar1); sr[2]=f.x; sr[3]=f.y;
            f = *reinterpret_cast<float2*>(&ar2); sr[4]=f.x; sr[5]=f.y;
            f = *reinterpret_cast<float2*>(&ar3); sr[6]=f.x; sr[7]=f.y;
            f = *reinterpret_cast<float2*>(&az0); sz[0]=f.x; sz[1]=f.y;
            f = *reinterpret_cast<float2*>(&az1); sz[2]=f.x; sz[3]=f.y;
            f = *reinterpret_cast<float2*>(&az2); sz[4]=f.x; sz[5]=f.y;
            f = *reinterpret_cast<float2*>(&az3); sz[6]=f.x; sz[7]=f.y;
            f = *reinterpret_cast<float2*>(&an0); sn[0]=f.x; sn[1]=f.y;
            f = *reinterpret_cast<float2*>(&an1); sn[2]=f.x; sn[3]=f.y;
            f = *reinterpret_cast<float2*>(&an2); sn[4]=f.x; sn[5]=f.y;
            f = *reinterpret_cast<float2*>(&an3); sn[6]=f.x; sn[7]=f.y;
        }

        float hnew[8];
        #pragma unroll
        for (int s2 = 0; s2 < 8; s2++) {
            float hold = h_t[c*8 + s2];
            float rpre = cr[s2] + sr[s2] + bh_r;
            float zpre = cz[s2] + sz[s2] + bh_z;
            float r = 1.f / (1.f + __expf(-rpre));
            float z = 1.f / (1.f + __expf(-zpre));
            float n = tanhf(cn[s2] + r * (sn[s2] + bh_n));
            hnew[s2] = (1.f - z) * n + z * hold;
        }
        __syncthreads();
        #pragma unroll
        for (int s2 = 0; s2 < 8; s2++) h_t[c*8 + s2] = hnew[s2];
        #pragma unroll
        for (int s2 = 0; s2 < 8; s2++) {
            int pix = dir ? ((b*64 + q0+s2)*64 + t) : ((b*64 + t)*64 + q0+s2);
            outp[(size_t)pix*DIMC + c] = hnew[s2];
        }
        __syncthreads();
    }
}

// ======================================================================
// Tail: scanned = oh+ow; gate GEMM + sigmoid; gated; proj_out GEMM +
// affine/relu + residual; transposed channel-major store.
// ======================================================================
#define TAIL_SMEM ((2*64*130 + 16*132 + 128*66) * 4)

__global__ void tail_kernel(const float* __restrict__ ohp,
                            const float* __restrict__ owp,
                            const float* __restrict__ xres,
                            const float* __restrict__ gate_w,
                            const float* __restrict__ gate_b,
                            const float* __restrict__ pw,
                            const float* __restrict__ pscale,
                            const float* __restrict__ pshift,
                            float* __restrict__ out)
{
    extern __shared__ float sm[];
    float* s_full = sm;                 // [64][130]
    float* g_full = sm + 64*130;        // [64][130]
    float* w_s    = sm + 2*64*130;      // [16][132]
    float* st     = w_s + 16*132;       // [128][66]

    const int m0  = blockIdx.x * 64;
    const int b   = m0 >> 12;
    const int hw0 = m0 & 4095;
    const int tid = threadIdx.x;
    const int tx = tid & 15, ty = tid >> 4;

    for (int i = tid; i < 64*32; i += 256) {
        int mm = i >> 5, kq = i & 31;
        float4 a = *(const float4*)(ohp + (size_t)(m0+mm)*DIMC + kq*4);
        float4 c = *(const float4*)(owp + (size_t)(m0+mm)*DIMC + kq*4);
        s_full[mm*130 + kq*4 + 0] = a.x + c.x;
        s_full[mm*130 + kq*4 + 1] = a.y + c.y;
        s_full[mm*130 + kq*4 + 2] = a.z + c.z;
        s_full[mm*130 + kq*4 + 3] = a.w + c.w;
    }
    __syncthreads();

    float acc[4][8];
    #pragma unroll
    for (int i = 0; i < 4; i++)
        #pragma unroll
        for (int j = 0; j < 8; j++) acc[i][j] = 0.f;

    for (int k0 = 0; k0 < 128; k0 += 16) {
        #pragma unroll
        for (int r = 0; r < 2; r++) {
            int id2 = tid + r*256;
            int nn = id2 >> 2, kq = id2 & 3;
            float4 v = *(const float4*)(gate_w + (size_t)nn*128 + k0 + kq*4);
            w_s[(kq*4+0)*132+nn] = v.x;
            w_s[(kq*4+1)*132+nn] = v.y;
            w_s[(kq*4+2)*132+nn] = v.z;
            w_s[(kq*4+3)*132+nn] = v.w;
        }
        __syncthreads();
        #pragma unroll
        for (int kk = 0; kk < 16; kk++) {
            float av[4], bv[8];
            #pragma unroll
            for (int i = 0; i < 4; i++) av[i] = s_full[(ty+16*i)*130 + k0 + kk];
            #pragma unroll
            for (int j = 0; j < 8; j++) bv[j] = w_s[kk*132 + tx + 16*j];
            #pragma unroll
            for (int i = 0; i < 4; i++)
                #pragma unroll
                for (int j = 0; j < 8; j++)
                    acc[i][j] = fmaf(av[i], bv[j], acc[i][j]);
        }
        __syncthreads();
    }

    #pragma unroll
    for (int i = 0; i < 4; i++) {
        int mm = ty + 16*i;
        #pragma unroll
        for (int j = 0; j < 8; j++) {
            int nn = tx + 16*j;
            float g = 1.f / (1.f + __expf(-(acc[i][j] + gate_b[nn])));
            g_full[mm*130 + nn] = s_full[mm*130 + nn] * g;
        }
    }
    __syncthreads();

    float acc2[4][8];
    #pragma unroll
    for (int i = 0; i < 4; i++)
        #pragma unroll
        for (int j = 0; j < 8; j++) acc2[i][j] = 0.f;

    for (int k0 = 0; k0 < 128; k0 += 16) {
        #pragma unroll
        for (int r = 0; r < 2; r++) {
            int id2 = tid + r*256;
            int nn = id2 >> 2, kq = id2 & 3;
            float4 v = *(const float4*)(pw + (size_t)nn*128 + k0 + kq*4);
            w_s[(kq*4+0)*132+nn] = v.x;
            w_s[(kq*4+1)*132+nn] = v.y;
            w_s[(kq*4+2)*132+nn] = v.z;
            w_s[(kq*4+3)*132+nn] = v.w;
        }
        __syncthreads();
        #pragma unroll
        for (int kk = 0; kk < 16; kk++) {
            float av[4], bv[8];
            #pragma unroll
            for (int i = 0; i < 4; i++) av[i] = g_full[(ty+16*i)*130 + k0 + kk];
            #pragma unroll
            for (int j = 0; j < 8; j++) bv[j] = w_s[kk*132 + tx + 16*j];
            #pragma unroll
            for (int i = 0; i < 4; i++)
                #pragma unroll
                for (int j = 0; j < 8; j++)
                    acc2[i][j] = fmaf(av[i], bv[j], acc2[i][j]);
        }
        __syncthreads();
    }

    #pragma unroll
    for (int i = 0; i < 4; i++) {
        int mm = ty + 16*i;
        #pragma unroll
        for (int j = 0; j < 8; j++) {
            int nn = tx + 16*j;
            float v = fmaxf(fmaf(acc2[i][j], pscale[nn], pshift[nn]), 0.f)
                    + xres[(size_t)(m0+mm)*DIMC + nn];
            st[nn*66 + mm] = v;
        }
    }
    __syncthreads();

    for (int i = tid; i < 128*64; i += 256) {
        int nn = i >> 6, mm = i & 63;
        out[(size_t)(b*128 + nn)*HW + hw0 + mm] = st[nn*66 + mm];
    }
}

// ======================================================================
// Launch
// ======================================================================
extern "C" void kernel_launch(void* const* d_in, const int* in_sizes, int n_in,
                              void* d_out, int out_size)
{
    const float* l     = (const float*)d_in[0];
    const float* m_    = (const float*)d_in[1];
    const float* s_    = (const float*)d_in[2];
    const float* piw   = (const float*)d_in[3];
    const float* pisc  = (const float*)d_in[4];
    const float* pish  = (const float*)d_in[5];
    const float* wih_h = (const float*)d_in[6];
    const float* whh_h = (const float*)d_in[7];
    const float* bih_h = (const float*)d_in[8];
    const float* bhh_h = (const float*)d_in[9];
    const float* wih_w = (const float*)d_in[10];
    const float* whh_w = (const float*)d_in[11];
    const float* bih_w = (const float*)d_in[12];
    const float* bhh_w = (const float*)d_in[13];
    const float* gw    = (const float*)d_in[14];
    const float* gb    = (const float*)d_in[15];
    const float* pow_  = (const float*)d_in[16];
    const float* posc  = (const float*)d_in[17];
    const float* posh  = (const float*)d_in[18];
    float* out = (float*)d_out;

    void *p_xcat, *p_x, *p_gxh, *p_gxw, *p_oh, *p_ow;
    cudaGetSymbolAddress(&p_xcat, g_xcat);
    cudaGetSymbolAddress(&p_x,    g_x);
    cudaGetSymbolAddress(&p_gxh,  g_gxh);
    cudaGetSymbolAddress(&p_gxw,  g_gxw);
    cudaGetSymbolAddress(&p_oh,   g_oh);
    cudaGetSymbolAddress(&p_ow,   g_ow);
    float* xcat = (float*)p_xcat;
    float* x    = (float*)p_x;
    float* gxh  = (float*)p_gxh;
    float* gxw  = (float*)p_gxw;
    float* oh   = (float*)p_oh;
    float* ow   = (float*)p_ow;

    cudaFuncSetAttribute(mma_proj_kernel, cudaFuncAttributeMaxDynamicSharedMemorySize, MMA_SMEM);
    cudaFuncSetAttribute(mma_gx_kernel,   cudaFuncAttributeMaxDynamicSharedMemorySize, MMA_SMEM);
    cudaFuncSetAttribute(scan_kernel,     cudaFuncAttributeMaxDynamicSharedMemorySize, SCAN_SMEM);
    cudaFuncSetAttribute(tail_kernel,     cudaFuncAttributeMaxDynamicSharedMemorySize, TAIL_SMEM);

    // 1. resize + concat
    resize_concat_kernel<<<(M_TOT*K3)/256, 256>>>(l, m_, s_, xcat);

    // 2. proj_in (bf16x3 warp MMA)
    mma_proj_kernel<<<M_TOT/128, 256, MMA_SMEM>>>(xcat, piw, pisc, pish, x);

    // 3. gx for both directions (bf16x3 warp MMA)
    mma_gx_kernel<<<dim3(M_TOT/128, 2), 256, MMA_SMEM>>>(x, wih_h, bih_h, wih_w, bih_w, gxh, gxw);

    // 4. both GRU scans (f32x2 packed FMA)
    scan_kernel<<<128, 128, SCAN_SMEM>>>(whh_h, bhh_h, whh_w, bhh_w, gxh, gxw, oh, ow);

    // 5. gate + proj_out + residual + transposed store
    tail_kernel<<<M_TOT/64, 256, TAIL_SMEM>>>(oh, ow, x, gw, gb, pow_, posc, posh, out);
}

// round 5
// speedup vs baseline: 1.9329x; 1.6569x over previous
#include <cuda_runtime.h>
#include <cuda_bf16.h>
#include <math.h>
#include <stdint.h>

// ---------------- problem constants ----------------
#define BATCH 8
#define DIMC 128
#define HGT 64
#define WID 64
#define HW 4096
#define M_TOT 32768       // BATCH*HGT*WID
#define K3 384

// ---------------- scratch ----------------
__device__ float g_xcat[M_TOT * K3];
__device__ float g_x[M_TOT * DIMC];
__device__ float g_gxh[M_TOT * K3];
__device__ float g_gxw[M_TOT * K3];
__device__ float g_oh[M_TOT * DIMC];
__device__ float g_ow[M_TOT * DIMC];

// ======================================================================
// helpers
// ======================================================================
__device__ __forceinline__ uint32_t smem_u32(const void* p) {
    uint32_t a;
    asm("{ .reg .u64 t; cvta.to.shared.u64 t, %1; cvt.u32.u64 %0, t; }"
        : "=r"(a) : "l"(p));
    return a;
}

__device__ __forceinline__ void ldsm4(uint32_t* r, uint32_t addr) {
    asm volatile("ldmatrix.sync.aligned.m8n8.x4.shared.b16 {%0,%1,%2,%3}, [%4];"
                 : "=r"(r[0]), "=r"(r[1]), "=r"(r[2]), "=r"(r[3]) : "r"(addr));
}

__device__ __forceinline__ void mma16816(float* c, const uint32_t* a, const uint32_t* b) {
    asm volatile(
        "mma.sync.aligned.m16n8k16.row.col.f32.bf16.bf16.f32 "
        "{%0,%1,%2,%3}, {%4,%5,%6,%7}, {%8,%9}, {%0,%1,%2,%3};"
        : "+f"(c[0]), "+f"(c[1]), "+f"(c[2]), "+f"(c[3])
        : "r"(a[0]), "r"(a[1]), "r"(a[2]), "r"(a[3]), "r"(b[0]), "r"(b[1]));
}

// convert float4 -> bf16 hi pair + bf16 lo-residual pair
__device__ __forceinline__ void cvt4(float4 v, uint2& hi, uint2& lo) {
    unsigned short b0 = __bfloat16_as_ushort(__float2bfloat16(v.x));
    unsigned short b1 = __bfloat16_as_ushort(__float2bfloat16(v.y));
    unsigned short b2 = __bfloat16_as_ushort(__float2bfloat16(v.z));
    unsigned short b3 = __bfloat16_as_ushort(__float2bfloat16(v.w));
    hi.x = ((uint32_t)b1 << 16) | (uint32_t)b0;
    hi.y = ((uint32_t)b3 << 16) | (uint32_t)b2;
    float r0 = v.x - __uint_as_float((uint32_t)b0 << 16);
    float r1 = v.y - __uint_as_float((uint32_t)b1 << 16);
    float r2 = v.z - __uint_as_float((uint32_t)b2 << 16);
    float r3 = v.w - __uint_as_float((uint32_t)b3 << 16);
    unsigned short c0 = __bfloat16_as_ushort(__float2bfloat16(r0));
    unsigned short c1 = __bfloat16_as_ushort(__float2bfloat16(r1));
    unsigned short c2 = __bfloat16_as_ushort(__float2bfloat16(r2));
    unsigned short c3 = __bfloat16_as_ushort(__float2bfloat16(r3));
    lo.x = ((uint32_t)c1 << 16) | (uint32_t)c0;
    lo.y = ((uint32_t)c3 << 16) | (uint32_t)c2;
}

// ======================================================================
// bf16x3 warp-MMA NT GEMM (coalesced staging)
// ======================================================================
#define SA_STRIDE 136
#define MMA_SMEM (104448)

template<int KSLABS, int NTILES, int EPI>
__device__ void mma_core(const float* __restrict__ A0, int lda,
                         const float* __restrict__ B0, int ldb,
                         const float* __restrict__ p0, const float* __restrict__ p1,
                         float* __restrict__ C0, int ldc)
{
    extern __shared__ char smraw[];
    __nv_bfloat16* sa_hi = (__nv_bfloat16*)(smraw);
    __nv_bfloat16* sa_lo = (__nv_bfloat16*)(smraw + 34816);
    __nv_bfloat16* sb_hi = (__nv_bfloat16*)(smraw + 69632);
    __nv_bfloat16* sb_lo = (__nv_bfloat16*)(smraw + 87040);
    const uint32_t sbase = smem_u32(smraw);
    const uint32_t u_sa_hi = sbase;
    const uint32_t u_sa_lo = sbase + 34816;
    const uint32_t u_sb_hi = sbase + 69632;
    const uint32_t u_sb_lo = sbase + 87040;

    const int tid  = threadIdx.x;
    const int wid  = tid >> 5;
    const int lane = tid & 31;
    const int wm = wid >> 1;
    const int wn = wid & 1;
    const int gid = lane >> 2, tig = lane & 3;
    const int col4 = (tid & 31) * 4;
    const int rbase = tid >> 5;

#pragma unroll 1
    for (int nt = 0; nt < NTILES; nt++) {
        float acc[2][4][4];
#pragma unroll
        for (int i = 0; i < 2; i++)
#pragma unroll
            for (int j = 0; j < 4; j++)
#pragma unroll
                for (int e = 0; e < 4; e++) acc[i][j][e] = 0.f;

#pragma unroll 1
        for (int s = 0; s < KSLABS; s++) {
            __syncthreads();
            if (nt == 0 || KSLABS > 1) {
#pragma unroll
                for (int j = 0; j < 16; j++) {
                    int r = rbase + 8 * j;
                    float4 v = *(const float4*)(A0 + (size_t)r * lda + s * 128 + col4);
                    uint2 hi, lo; cvt4(v, hi, lo);
                    *(uint2*)(sa_hi + r * SA_STRIDE + col4) = hi;
                    *(uint2*)(sa_lo + r * SA_STRIDE + col4) = lo;
                }
            }
            {
#pragma unroll
                for (int j = 0; j < 8; j++) {
                    int r = rbase + 8 * j;
                    float4 v = *(const float4*)(B0 + (size_t)(nt * 64 + r) * ldb + s * 128 + col4);
                    uint2 hi, lo; cvt4(v, hi, lo);
                    *(uint2*)(sb_hi + r * SA_STRIDE + col4) = hi;
                    *(uint2*)(sb_lo + r * SA_STRIDE + col4) = lo;
                }
            }
            __syncthreads();

#pragma unroll
            for (int ch = 0; ch < 8; ch++) {
                const int k = ch * 16;
                uint32_t ah[2][4], al[2][4];
#pragma unroll
                for (int i = 0; i < 2; i++) {
                    uint32_t off = (uint32_t)(((wm*32 + i*16 + (lane & 15)) * SA_STRIDE
                                               + k + ((lane >> 4) << 3)) * 2);
                    ldsm4(ah[i], u_sa_hi + off);
                    ldsm4(al[i], u_sa_lo + off);
                }
                uint32_t bh[4][2], bl[4][2];
#pragma unroll
                for (int nb = 0; nb < 2; nb++) {
                    int row = wn*32 + nb*16 + (lane & 7) + ((lane >> 4) << 3);
                    int col = k + ((lane >> 3) & 1) * 8;
                    uint32_t off = (uint32_t)((row * SA_STRIDE + col) * 2);
                    uint32_t r[4];
                    ldsm4(r, u_sb_hi + off);
                    bh[2*nb][0] = r[0]; bh[2*nb][1] = r[1];
                    bh[2*nb+1][0] = r[2]; bh[2*nb+1][1] = r[3];
                    ldsm4(r, u_sb_lo + off);
                    bl[2*nb][0] = r[0]; bl[2*nb][1] = r[1];
                    bl[2*nb+1][0] = r[2]; bl[2*nb+1][1] = r[3];
                }
#pragma unroll
                for (int i = 0; i < 2; i++)
#pragma unroll
                    for (int j = 0; j < 4; j++) {
                        mma16816(acc[i][j], ah[i], bh[j]);
                        mma16816(acc[i][j], ah[i], bl[j]);
                        mma16816(acc[i][j], al[i], bh[j]);
                    }
            }
        }

#pragma unroll
        for (int i = 0; i < 2; i++) {
            int mrow = wm*32 + i*16 + gid;
#pragma unroll
            for (int j = 0; j < 4; j++) {
                int ncol = nt*64 + wn*32 + j*8 + tig*2;
                float2 q0 = *(const float2*)(p0 + ncol);
                float2 q1 = (EPI == 0) ? *(const float2*)(p1 + ncol)
                                       : make_float2(0.f, 0.f);
                float v0, v1, v2, v3;
                if (EPI == 0) {
                    v0 = fmaxf(fmaf(acc[i][j][0], q0.x, q1.x), 0.f);
                    v1 = fmaxf(fmaf(acc[i][j][1], q0.y, q1.y), 0.f);
                    v2 = fmaxf(fmaf(acc[i][j][2], q0.x, q1.x), 0.f);
                    v3 = fmaxf(fmaf(acc[i][j][3], q0.y, q1.y), 0.f);
                } else {
                    v0 = acc[i][j][0] + q0.x;
                    v1 = acc[i][j][1] + q0.y;
                    v2 = acc[i][j][2] + q0.x;
                    v3 = acc[i][j][3] + q0.y;
                }
                *(float2*)(C0 + (size_t)mrow * ldc + ncol) = make_float2(v0, v1);
                *(float2*)(C0 + (size_t)(mrow + 8) * ldc + ncol) = make_float2(v2, v3);
            }
        }
    }
}

__global__ void __launch_bounds__(256)
mma_proj_kernel(const float* __restrict__ xcat, const float* __restrict__ piw,
                const float* __restrict__ pisc, const float* __restrict__ pish,
                float* __restrict__ x)
{
    mma_core<3, 2, 0>(xcat + (size_t)blockIdx.x * 128 * K3, K3,
                      piw, K3, pisc, pish,
                      x + (size_t)blockIdx.x * 128 * DIMC, DIMC);
}

__global__ void __launch_bounds__(256)
mma_gx_kernel(const float* __restrict__ x,
              const float* __restrict__ wih_h, const float* __restrict__ bih_h,
              const float* __restrict__ wih_w, const float* __restrict__ bih_w,
              float* __restrict__ gxh, float* __restrict__ gxw)
{
    const float* B    = blockIdx.y ? wih_w : wih_h;
    const float* bias = blockIdx.y ? bih_w : bih_h;
    float* out        = blockIdx.y ? gxw : gxh;
    mma_core<1, 6, 1>(x + (size_t)blockIdx.x * 128 * DIMC, DIMC,
                      B, DIMC, bias, nullptr,
                      out + (size_t)blockIdx.x * 128 * K3, K3);
}

// ======================================================================
// resize + concat, coalesced: one block per (b,h) row, lanes along w.
// 6 chunks of 64 channels: [0,128) l-down, [128,256) m copy, [256,384) s-up.
// ======================================================================
__global__ void __launch_bounds__(256)
resize_concat_kernel(const float* __restrict__ l,
                     const float* __restrict__ mid,
                     const float* __restrict__ s,
                     float* __restrict__ xcat)
{
    __shared__ float st[64 * 65];
    const int bh = blockIdx.x;          // b*64 + h
    const int b = bh >> 6, h = bh & 63;
    const int tid = threadIdx.x;
    const int wq = tid & 63;            // w coordinate (compute phase)
    const int cl = tid >> 6;            // 0..3

    // --- tap setup (per thread; depends only on h, wq) ---
    // l: 4-tap antialias triangle
    int ljh[4]; float lwh[4];
    int ljw[4]; float lww[4];
    {
        float sum = 0.f;
#pragma unroll
        for (int t = 0; t < 4; t++) {
            int jj = 2*h - 1 + t;
            float r = (t == 0 || t == 3) ? 0.25f : 0.75f;
            bool ok = (jj >= 0 && jj < 128);
            ljh[t] = ok ? jj : 0;
            lwh[t] = ok ? r : 0.f;
            sum += lwh[t];
        }
        float inv = 1.f / sum;
#pragma unroll
        for (int t = 0; t < 4; t++) lwh[t] *= inv;
    }
    {
        float sum = 0.f;
#pragma unroll
        for (int t = 0; t < 4; t++) {
            int jj = 2*wq - 1 + t;
            float r = (t == 0 || t == 3) ? 0.25f : 0.75f;
            bool ok = (jj >= 0 && jj < 128);
            ljw[t] = ok ? jj : 0;
            lww[t] = ok ? r : 0.f;
            sum += lww[t];
        }
        float inv = 1.f / sum;
#pragma unroll
        for (int t = 0; t < 4; t++) lww[t] *= inv;
    }
    // s: 2-tap bilinear up
    int sjh[2]; float swh[2];
    int sjw[2]; float sww[2];
    {
        float p = 0.5f*h - 0.25f;
        int j0 = (int)floorf(p);
        float f = p - (float)j0;
        bool o0 = (j0 >= 0 && j0 < 32), o1 = (j0+1 >= 0 && j0+1 < 32);
        swh[0] = o0 ? (1.f - f) : 0.f; sjh[0] = o0 ? j0 : 0;
        swh[1] = o1 ? f : 0.f;         sjh[1] = o1 ? (j0+1) : 0;
        float inv = 1.f / (swh[0] + swh[1]);
        swh[0] *= inv; swh[1] *= inv;
    }
    {
        float p = 0.5f*wq - 0.25f;
        int j0 = (int)floorf(p);
        float f = p - (float)j0;
        bool o0 = (j0 >= 0 && j0 < 32), o1 = (j0+1 >= 0 && j0+1 < 32);
        sww[0] = o0 ? (1.f - f) : 0.f; sjw[0] = o0 ? j0 : 0;
        sww[1] = o1 ? f : 0.f;         sjw[1] = o1 ? (j0+1) : 0;
        float inv = 1.f / (sww[0] + sww[1]);
        sww[0] *= inv; sww[1] *= inv;
    }

    const int ww = tid >> 2;            // write-phase w
    const int c0 = (tid & 3) * 16;      // write-phase channel base

#pragma unroll 1
    for (int chunk = 0; chunk < 6; chunk++) {
        const int cbase = chunk * 64;
        // compute 16 channels (c_local = cl + 4*i) at (h, wq)
        if (chunk < 2) {
#pragma unroll 4
            for (int i = 0; i < 16; i++) {
                int c = cbase + cl + 4*i;
                const float* lp = l + ((size_t)(b*128 + c) << 14);
                float v = 0.f;
#pragma unroll
                for (int a = 0; a < 4; a++) {
                    const float* row = lp + (ljh[a] << 7);
                    float ra = lww[0]*row[ljw[0]] + lww[1]*row[ljw[1]]
                             + lww[2]*row[ljw[2]] + lww[3]*row[ljw[3]];
                    v = fmaf(lwh[a], ra, v);
                }
                st[(cl + 4*i) * 65 + wq] = v;
            }
        } else if (chunk < 4) {
#pragma unroll 4
            for (int i = 0; i < 16; i++) {
                int c = cbase - 128 + cl + 4*i;
                st[(cl + 4*i) * 65 + wq] =
                    mid[((size_t)(b*128 + c) << 12) + (h << 6) + wq];
            }
        } else {
#pragma unroll 4
            for (int i = 0; i < 16; i++) {
                int c = cbase - 256 + cl + 4*i;
                const float* sp = s + ((size_t)(b*128 + c) << 10);
                const float* r0 = sp + (sjh[0] << 5);
                const float* r1 = sp + (sjh[1] << 5);
                float v = swh[0]*(sww[0]*r0[sjw[0]] + sww[1]*r0[sjw[1]])
                        + swh[1]*(sww[0]*r1[sjw[0]] + sww[1]*r1[sjw[1]]);
                st[(cl + 4*i) * 65 + wq] = v;
            }
        }
        __syncthreads();
        // write phase: xcat[(bh*64 + ww)*384 + cbase + c0 .. +15]
        float* dst = xcat + (size_t)(bh*64 + ww) * K3 + cbase + c0;
#pragma unroll
        for (int j = 0; j < 4; j++) {
            int cc = c0 + 4*j;
            float4 v = make_float4(st[(cc+0)*65 + ww], st[(cc+1)*65 + ww],
                                   st[(cc+2)*65 + ww], st[(cc+3)*65 + ww]);
            *(float4*)(dst + 4*j) = v;
        }
        __syncthreads();
    }
}

// ======================================================================
// Scan kernel: 128 blocks x 384 threads (gate-split).
// Thread g owns gate-row g of whh; tail (g<128) owns channel g, h in regs.
// ======================================================================
#define SCAN_SMEM ((384*129 + 384*9 + 128*8) * 4)

#define FMA2(acc, a, b) \
    asm volatile("fma.rn.f32x2 %0, %1, %2, %0;" : "+l"(acc) : "l"(a), "l"(b))
#define PACK2(d, f) \
    asm volatile("mov.b64 %0, {%1, %1};" : "=l"(d) : "r"(__float_as_uint(f)))

__global__ void __launch_bounds__(384, 1)
scan_kernel(const float* __restrict__ whh_h,
            const float* __restrict__ bhh_h,
            const float* __restrict__ whh_w,
            const float* __restrict__ bhh_w,
            const float* __restrict__ gxh,
            const float* __restrict__ gxw,
            float* __restrict__ ohp,
            float* __restrict__ owp)
{
    extern __shared__ float sm[];
    float* whh_s = sm;                  // [384][129]
    float* sg    = sm + 384*129;        // [384][9]
    float* hbuf  = sm + 384*129 + 384*9; // [128][8]

    const int dir = blockIdx.x >> 6;
    const int sub = blockIdx.x & 63;
    const int b   = sub >> 3;
    const int q0  = (sub & 7) << 3;

    const float* whh = dir ? whh_w : whh_h;
    const float* bhh = dir ? bhh_w : bhh_h;
    const float* gx  = dir ? gxw : gxh;
    float* outp      = dir ? owp : ohp;

    const int g = threadIdx.x;          // 0..383

    for (int i = g; i < 384*32; i += 384) {
        int r = i >> 5, q = i & 31;
        float4 v = *(const float4*)(whh + r*128 + q*4);
        whh_s[r*129 + q*4 + 0] = v.x;
        whh_s[r*129 + q*4 + 1] = v.y;
        whh_s[r*129 + q*4 + 2] = v.z;
        whh_s[r*129 + q*4 + 3] = v.w;
    }
    if (g < 128) {
#pragma unroll
        for (int s2 = 0; s2 < 8; s2++) hbuf[g*8 + s2] = 0.f;
    }
    const float bh = bhh[g];
    __syncthreads();

    const float* wg = whh_s + (size_t)g * 129;

#define PIXAT(t, s2) (dir ? ((b*64 + q0+(s2))*64 + (t)) : ((b*64 + (t))*64 + q0+(s2)))

    float nx[8], ncn[8];
    float hreg[8];
#pragma unroll
    for (int s2 = 0; s2 < 8; s2++) hreg[s2] = 0.f;

    if (g < 256) {
#pragma unroll
        for (int s2 = 0; s2 < 8; s2++)
            nx[s2] = gx[(size_t)PIXAT(0, s2) * K3 + g];
    }
    if (g < 128) {
#pragma unroll
        for (int s2 = 0; s2 < 8; s2++)
            ncn[s2] = gx[(size_t)PIXAT(0, s2) * K3 + 256 + g];
    }

    for (int t = 0; t < 64; t++) {
        float cx[8], ccn[8];
        if (g < 256) {
#pragma unroll
            for (int s2 = 0; s2 < 8; s2++) cx[s2] = nx[s2];
        }
        if (g < 128) {
#pragma unroll
            for (int s2 = 0; s2 < 8; s2++) ccn[s2] = ncn[s2];
        }
        if (t < 63) {
            if (g < 256) {
#pragma unroll
                for (int s2 = 0; s2 < 8; s2++)
                    nx[s2] = gx[(size_t)PIXAT(t+1, s2) * K3 + g];
            }
            if (g < 128) {
#pragma unroll
                for (int s2 = 0; s2 < 8; s2++)
                    ncn[s2] = gx[(size_t)PIXAT(t+1, s2) * K3 + 256 + g];
            }
        }

        unsigned long long a0 = 0, a1 = 0, a2 = 0, a3 = 0;
#pragma unroll 8
        for (int k = 0; k < 128; k++) {
            const ulonglong2* hp = reinterpret_cast<const ulonglong2*>(hbuf + k*8);
            ulonglong2 hA = hp[0];
            ulonglong2 hB = hp[1];
            unsigned long long w2;
            PACK2(w2, wg[k]);
            FMA2(a0, hA.x, w2); FMA2(a1, hA.y, w2);
            FMA2(a2, hB.x, w2); FMA2(a3, hB.y, w2);
        }
        float sv[8];
        {
            float2 f;
            f = *reinterpret_cast<float2*>(&a0); sv[0] = f.x; sv[1] = f.y;
            f = *reinterpret_cast<float2*>(&a1); sv[2] = f.x; sv[3] = f.y;
            f = *reinterpret_cast<float2*>(&a2); sv[4] = f.x; sv[5] = f.y;
            f = *reinterpret_cast<float2*>(&a3); sv[6] = f.x; sv[7] = f.y;
        }
        if (g < 256) {
#pragma unroll
            for (int s2 = 0; s2 < 8; s2++)
                sg[g*9 + s2] = sv[s2] + bh + cx[s2];
        } else {
#pragma unroll
            for (int s2 = 0; s2 < 8; s2++)
                sg[g*9 + s2] = sv[s2] + bh;
        }
        __syncthreads();

        if (g < 128) {
#pragma unroll
            for (int s2 = 0; s2 < 8; s2++) {
                float rp = sg[g*9 + s2];
                float zp = sg[(g+128)*9 + s2];
                float sn = sg[(g+256)*9 + s2];
                float er = __expf(-rp);
                float ez = __expf(-zp);
                float r = __fdividef(1.f, 1.f + er);
                float z = __fdividef(1.f, 1.f + ez);
                float xn = ccn[s2] + r * sn;
                float en = __expf(2.f * xn);
                float n = 1.f - __fdividef(2.f, en + 1.f);
                float hnew = (1.f - z) * n + z * hreg[s2];
                hreg[s2] = hnew;
                hbuf[g*8 + s2] = hnew;
                outp[(size_t)PIXAT(t, s2) * DIMC + g] = hnew;
            }
        }
        __syncthreads();
    }
#undef PIXAT
}

// ======================================================================
// Tail: scanned = oh+ow; gate GEMM + sigmoid; gated; proj_out GEMM +
// affine/relu + residual; transposed channel-major store.
// ======================================================================
#define TAIL_SMEM ((2*64*130 + 16*132 + 128*66) * 4)

__global__ void tail_kernel(const float* __restrict__ ohp,
                            const float* __restrict__ owp,
                            const float* __restrict__ xres,
                            const float* __restrict__ gate_w,
                            const float* __restrict__ gate_b,
                            const float* __restrict__ pw,
                            const float* __restrict__ pscale,
                            const float* __restrict__ pshift,
                            float* __restrict__ out)
{
    extern __shared__ float sm[];
    float* s_full = sm;                 // [64][130]
    float* g_full = sm + 64*130;        // [64][130]
    float* w_s    = sm + 2*64*130;      // [16][132]
    float* st     = w_s + 16*132;       // [128][66]

    const int m0  = blockIdx.x * 64;
    const int b   = m0 >> 12;
    const int hw0 = m0 & 4095;
    const int tid = threadIdx.x;
    const int tx = tid & 15, ty = tid >> 4;

    for (int i = tid; i < 64*32; i += 256) {
        int mm = i >> 5, kq = i & 31;
        float4 a = *(const float4*)(ohp + (size_t)(m0+mm)*DIMC + kq*4);
        float4 c = *(const float4*)(owp + (size_t)(m0+mm)*DIMC + kq*4);
        s_full[mm*130 + kq*4 + 0] = a.x + c.x;
        s_full[mm*130 + kq*4 + 1] = a.y + c.y;
        s_full[mm*130 + kq*4 + 2] = a.z + c.z;
        s_full[mm*130 + kq*4 + 3] = a.w + c.w;
    }
    __syncthreads();

    float acc[4][8];
    #pragma unroll
    for (int i = 0; i < 4; i++)
        #pragma unroll
        for (int j = 0; j < 8; j++) acc[i][j] = 0.f;

    for (int k0 = 0; k0 < 128; k0 += 16) {
        #pragma unroll
        for (int r = 0; r < 2; r++) {
            int id2 = tid + r*256;
            int nn = id2 >> 2, kq = id2 & 3;
            float4 v = *(const float4*)(gate_w + (size_t)nn*128 + k0 + kq*4);
            w_s[(kq*4+0)*132+nn] = v.x;
            w_s[(kq*4+1)*132+nn] = v.y;
            w_s[(kq*4+2)*132+nn] = v.z;
            w_s[(kq*4+3)*132+nn] = v.w;
        }
        __syncthreads();
        #pragma unroll
        for (int kk = 0; kk < 16; kk++) {
            float av[4], bv[8];
            #pragma unroll
            for (int i = 0; i < 4; i++) av[i] = s_full[(ty+16*i)*130 + k0 + kk];
            #pragma unroll
            for (int j = 0; j < 8; j++) bv[j] = w_s[kk*132 + tx + 16*j];
            #pragma unroll
            for (int i = 0; i < 4; i++)
                #pragma unroll
                for (int j = 0; j < 8; j++)
                    acc[i][j] = fmaf(av[i], bv[j], acc[i][j]);
        }
        __syncthreads();
    }

    #pragma unroll
    for (int i = 0; i < 4; i++) {
        int mm = ty + 16*i;
        #pragma unroll
        for (int j = 0; j < 8; j++) {
            int nn = tx + 16*j;
            float e = __expf(-(acc[i][j] + gate_b[nn]));
            float gsig = __fdividef(1.f, 1.f + e);
            g_full[mm*130 + nn] = s_full[mm*130 + nn] * gsig;
        }
    }
    __syncthreads();

    float acc2[4][8];
    #pragma unroll
    for (int i = 0; i < 4; i++)
        #pragma unroll
        for (int j = 0; j < 8; j++) acc2[i][j] = 0.f;

    for (int k0 = 0; k0 < 128; k0 += 16) {
        #pragma unroll
        for (int r = 0; r < 2; r++) {
            int id2 = tid + r*256;
            int nn = id2 >> 2, kq = id2 & 3;
            float4 v = *(const float4*)(pw + (size_t)nn*128 + k0 + kq*4);
            w_s[(kq*4+0)*132+nn] = v.x;
            w_s[(kq*4+1)*132+nn] = v.y;
            w_s[(kq*4+2)*132+nn] = v.z;
            w_s[(kq*4+3)*132+nn] = v.w;
        }
        __syncthreads();
        #pragma unroll
        for (int kk = 0; kk < 16; kk++) {
            float av[4], bv[8];
            #pragma unroll
            for (int i = 0; i < 4; i++) av[i] = g_full[(ty+16*i)*130 + k0 + kk];
            #pragma unroll
            for (int j = 0; j < 8; j++) bv[j] = w_s[kk*132 + tx + 16*j];
            #pragma unroll
            for (int i = 0; i < 4; i++)
                #pragma unroll
                for (int j = 0; j < 8; j++)
                    acc2[i][j] = fmaf(av[i], bv[j], acc2[i][j]);
        }
        __syncthreads();
    }

    #pragma unroll
    for (int i = 0; i < 4; i++) {
        int mm = ty + 16*i;
        #pragma unroll
        for (int j = 0; j < 8; j++) {
            int nn = tx + 16*j;
            float v = fmaxf(fmaf(acc2[i][j], pscale[nn], pshift[nn]), 0.f)
                    + xres[(size_t)(m0+mm)*DIMC + nn];
            st[nn*66 + mm] = v;
        }
    }
    __syncthreads();

    for (int i = tid; i < 128*64; i += 256) {
        int nn = i >> 6, mm = i & 63;
        out[(size_t)(b*128 + nn)*HW + hw0 + mm] = st[nn*66 + mm];
    }
}

// ======================================================================
// Launch
// ======================================================================
extern "C" void kernel_launch(void* const* d_in, const int* in_sizes, int n_in,
                              void* d_out, int out_size)
{
    const float* l     = (const float*)d_in[0];
    const float* m_    = (const float*)d_in[1];
    const float* s_    = (const float*)d_in[2];
    const float* piw   = (const float*)d_in[3];
    const float* pisc  = (const float*)d_in[4];
    const float* pish  = (const float*)d_in[5];
    const float* wih_h = (const float*)d_in[6];
    const float* whh_h = (const float*)d_in[7];
    const float* bih_h = (const float*)d_in[8];
    const float* bhh_h = (const float*)d_in[9];
    const float* wih_w = (const float*)d_in[10];
    const float* whh_w = (const float*)d_in[11];
    const float* bih_w = (const float*)d_in[12];
    const float* bhh_w = (const float*)d_in[13];
    const float* gw    = (const float*)d_in[14];
    const float* gb    = (const float*)d_in[15];
    const float* pow_  = (const float*)d_in[16];
    const float* posc  = (const float*)d_in[17];
    const float* posh  = (const float*)d_in[18];
    float* out = (float*)d_out;

    void *p_xcat, *p_x, *p_gxh, *p_gxw, *p_oh, *p_ow;
    cudaGetSymbolAddress(&p_xcat, g_xcat);
    cudaGetSymbolAddress(&p_x,    g_x);
    cudaGetSymbolAddress(&p_gxh,  g_gxh);
    cudaGetSymbolAddress(&p_gxw,  g_gxw);
    cudaGetSymbolAddress(&p_oh,   g_oh);
    cudaGetSymbolAddress(&p_ow,   g_ow);
    float* xcat = (float*)p_xcat;
    float* x    = (float*)p_x;
    float* gxh  = (float*)p_gxh;
    float* gxw  = (float*)p_gxw;
    float* oh   = (float*)p_oh;
    float* ow   = (float*)p_ow;

    cudaFuncSetAttribute(mma_proj_kernel, cudaFuncAttributeMaxDynamicSharedMemorySize, MMA_SMEM);
    cudaFuncSetAttribute(mma_gx_kernel,   cudaFuncAttributeMaxDynamicSharedMemorySize, MMA_SMEM);
    cudaFuncSetAttribute(scan_kernel,     cudaFuncAttributeMaxDynamicSharedMemorySize, SCAN_SMEM);
    cudaFuncSetAttribute(tail_kernel,     cudaFuncAttributeMaxDynamicSharedMemorySize, TAIL_SMEM);

    // 1. resize + concat (coalesced, lanes along w)
    resize_concat_kernel<<<BATCH*HGT, 256>>>(l, m_, s_, xcat);

    // 2. proj_in (bf16x3 warp MMA)
    mma_proj_kernel<<<M_TOT/128, 256, MMA_SMEM>>>(xcat, piw, pisc, pish, x);

    // 3. gx for both directions (bf16x3 warp MMA)
    mma_gx_kernel<<<dim3(M_TOT/128, 2), 256, MMA_SMEM>>>(x, wih_h, bih_h, wih_w, bih_w, gxh, gxw);

    // 4. both GRU scans (gate-split, f32x2 packed FMA, 12 warps/block)
    scan_kernel<<<128, 384, SCAN_SMEM>>>(whh_h, bhh_h, whh_w, bhh_w, gxh, gxw, oh, ow);

    // 5. gate + proj_out + residual + transposed store
    tail_kernel<<<M_TOT/64, 256, TAIL_SMEM>>>(oh, ow, x, gw, gb, pow_, posc, posh, out);
}